// round 2
// baseline (speedup 1.0000x reference)
#include <cuda_runtime.h>
#include <cuda_bf16.h>

// ---------------------------------------------------------------------------
// AAconv: 3x (AugmentedConv + ReLU[first two]) + FC head.
// Shapes fixed: B=16, S=32 (HW=1024), DK=16, DV=4, NH=4 => dkh=4, dvh=1.
// Layers: (ci, co) = (8,32), (32,32), (32,6); conv_oc = co-4; qkv_oc = 36.
// ---------------------------------------------------------------------------

#define BATCH 16
#define HW 1024

// Scratch (device globals; allocation-free per harness rules)
__device__ float g_x[BATCH * 32 * HW];      // layer intermediate (max co=32)
__device__ float g_conv[BATCH * 28 * HW];   // conv branch (max co_conv=28)
__device__ float g_qkv[BATCH * 36 * HW];    // qkv buffer
__device__ float g_attn[BATCH * 4 * HW];    // per-head attention output (dvh=1)

// ---------------------------------------------------------------------------
// Fused 3x3 conv: computes conv_out (CO_CONV ch) and qkv (36 ch) from input.
// Block: 256 threads, one (batch, oc-group-of-8). Smem input tile w/ halo,
// ci chunks of 8, register accumulators (8 oc x 4 px / thread).
// ---------------------------------------------------------------------------
__global__ __launch_bounds__(256) void conv_fused(
    const float* __restrict__ in_ext, int use_internal, int CI,
    const float* __restrict__ wc, const float* __restrict__ bc, int CO_CONV,
    const float* __restrict__ wq, const float* __restrict__ bq)
{
    const float* __restrict__ in = use_internal ? g_x : in_ext;
    const int b   = blockIdx.x;
    const int oc0 = blockIdx.y * 8;
    const int OC_TOT = CO_CONV + 36;

    __shared__ float tile[8][34][35];   // +1 pad (stride 35, gcd(5,32)=1)
    __shared__ float ws[8][8][9];
    __shared__ float wb[8];

    const int tid = threadIdx.x;
    if (tid < 8) {
        int oc = oc0 + tid;
        float bv = 0.f;
        if (oc < OC_TOT) bv = (oc < CO_CONV) ? bc[oc] : bq[oc - CO_CONV];
        wb[tid] = bv;
    }

    float acc[8][4];
#pragma unroll
    for (int o = 0; o < 8; o++)
#pragma unroll
        for (int p = 0; p < 4; p++) acc[o][p] = 0.f;

    const int y  = tid >> 3;        // 0..31
    const int xq = (tid & 7) * 4;   // 0,4,...,28

    for (int ci0 = 0; ci0 < CI; ci0 += 8) {
        // weights for this (oc-group, ci-chunk)
        for (int w = tid; w < 8 * 8 * 9; w += 256) {
            int o = w / 72;
            int r = w - o * 72;
            int c = r / 9, tap = r - c * 9;
            int oc = oc0 + o;
            float val = 0.f;
            if (oc < OC_TOT) {
                if (oc < CO_CONV) val = wc[(oc * CI + ci0 + c) * 9 + tap];
                else              val = wq[((oc - CO_CONV) * CI + ci0 + c) * 9 + tap];
            }
            ws[o][c][tap] = val;
        }
        // input tile (34x34 with zero halo) for 8 channels
        for (int e = tid; e < 8 * 34 * 34; e += 256) {
            int c = e / 1156;
            int r = e - c * 1156;
            int yy = r / 34, xx = r - yy * 34;
            int gy = yy - 1, gx = xx - 1;
            float v = 0.f;
            if ((unsigned)gy < 32u && (unsigned)gx < 32u)
                v = in[((b * CI + ci0 + c) << 10) + gy * 32 + gx];
            tile[c][yy][xx] = v;
        }
        __syncthreads();

#pragma unroll
        for (int c = 0; c < 8; c++) {
            float p[3][6];
#pragma unroll
            for (int dy = 0; dy < 3; dy++)
#pragma unroll
                for (int dx = 0; dx < 6; dx++)
                    p[dy][dx] = tile[c][y + dy][xq + dx];
#pragma unroll
            for (int o = 0; o < 8; o++) {
                float w0 = ws[o][c][0], w1 = ws[o][c][1], w2 = ws[o][c][2];
                float w3 = ws[o][c][3], w4 = ws[o][c][4], w5 = ws[o][c][5];
                float w6 = ws[o][c][6], w7 = ws[o][c][7], w8 = ws[o][c][8];
#pragma unroll
                for (int px = 0; px < 4; px++) {
                    float a = acc[o][px];
                    a = fmaf(w0, p[0][px], a);
                    a = fmaf(w1, p[0][px + 1], a);
                    a = fmaf(w2, p[0][px + 2], a);
                    a = fmaf(w3, p[1][px], a);
                    a = fmaf(w4, p[1][px + 1], a);
                    a = fmaf(w5, p[1][px + 2], a);
                    a = fmaf(w6, p[2][px], a);
                    a = fmaf(w7, p[2][px + 1], a);
                    a = fmaf(w8, p[2][px + 2], a);
                    acc[o][px] = a;
                }
            }
        }
        __syncthreads();
    }

#pragma unroll
    for (int o = 0; o < 8; o++) {
        int oc = oc0 + o;
        if (oc >= OC_TOT) continue;
        float bv = wb[o];
        float4 v4 = make_float4(acc[o][0] + bv, acc[o][1] + bv,
                                acc[o][2] + bv, acc[o][3] + bv);
        float* dst = (oc < CO_CONV)
            ? (g_conv + ((b * CO_CONV + oc) << 10))
            : (g_qkv  + ((b * 36 + (oc - CO_CONV)) << 10));
        *reinterpret_cast<float4*>(dst + y * 32 + xq) = v4;
    }
}

// ---------------------------------------------------------------------------
// Fused attention with relative position logits + softmax + PV.
// logit(i=(x,y), j=(xk,yk)) = q_i.k_j + q_i.rel_w[yk-y+31] + q_i.rel_h[xk-x+31]
// Key j = t*32+lane -> yk=lane (lane-constant rel_w term), xk=t (shfl rel_h).
// Block: 256 thr = 8 warps, each warp handles 32 queries; one (b, head, chunk).
// ---------------------------------------------------------------------------
__global__ __launch_bounds__(256) void attn_kernel(
    const float* __restrict__ relw, const float* __restrict__ relh)
{
    const int chunk = blockIdx.x;  // 0..3
    const int n = blockIdx.y;      // head 0..3
    const int b = blockIdx.z;

    __shared__ float4 ks[1024];
    __shared__ float  vs[1024];
    __shared__ float  rws[63][5];  // pad to 5 -> conflict-free (gcd(5,32)=1)
    __shared__ float  rhs[63][5];

    const int tid = threadIdx.x;
    const float* kbase = g_qkv + ((size_t)(b * 36 + 16 + n * 4) << 10);
    const float* vbase = g_qkv + ((size_t)(b * 36 + 32 + n) << 10);
    for (int j = tid; j < 1024; j += 256) {
        ks[j] = make_float4(kbase[j], kbase[j + 1024], kbase[j + 2048], kbase[j + 3072]);
        vs[j] = vbase[j];
    }
    for (int e = tid; e < 252; e += 256) {
        rws[e >> 2][e & 3] = __ldg(relw + e);
        rhs[e >> 2][e & 3] = __ldg(relh + e);
    }
    __syncthreads();

    const int warp = tid >> 5, lane = tid & 31;
    const float* qbase = g_qkv + ((size_t)(b * 36 + n * 4) << 10);

    for (int it = 0; it < 32; it++) {
        const int i = chunk * 256 + warp * 32 + it;
        const float q0 = __ldg(qbase + i) * 0.5f;
        const float q1 = __ldg(qbase + i + 1024) * 0.5f;
        const float q2 = __ldg(qbase + i + 2048) * 0.5f;
        const float q3 = __ldg(qbase + i + 3072) * 0.5f;
        const int x = i >> 5, y = i & 31;

        const float* rw = rws[lane - y + 31];
        const float rw_own = q0 * rw[0] + q1 * rw[1] + q2 * rw[2] + q3 * rw[3];
        const float* rh = rhs[lane - x + 31];
        const float rh_own = q0 * rh[0] + q1 * rh[1] + q2 * rh[2] + q3 * rh[3];

        float s[32];
        float m = -1e30f;
#pragma unroll
        for (int t = 0; t < 32; t++) {
            float4 kk = ks[t * 32 + lane];
            float rh_t = __shfl_sync(0xffffffffu, rh_own, t);
            float v = fmaf(q0, kk.x, fmaf(q1, kk.y, fmaf(q2, kk.z, q3 * kk.w)))
                      + rw_own + rh_t;
            s[t] = v;
            m = fmaxf(m, v);
        }
#pragma unroll
        for (int o = 16; o; o >>= 1)
            m = fmaxf(m, __shfl_xor_sync(0xffffffffu, m, o));

        float l = 0.f, a = 0.f;
#pragma unroll
        for (int t = 0; t < 32; t++) {
            float p = __expf(s[t] - m);
            l += p;
            a = fmaf(p, vs[t * 32 + lane], a);
        }
#pragma unroll
        for (int o = 16; o; o >>= 1) {
            l += __shfl_xor_sync(0xffffffffu, l, o);
            a += __shfl_xor_sync(0xffffffffu, a, o);
        }
        if (lane == 0) g_attn[((b * 4 + n) << 10) + i] = a / l;
    }
}

// ---------------------------------------------------------------------------
// Mid-layer combine: concat(conv_out, 1x1conv(attn)) + ReLU -> g_x
// ---------------------------------------------------------------------------
__global__ __launch_bounds__(256) void combine_mid(
    int co_conv, const float* __restrict__ attn_w,
    const float* __restrict__ attn_b, int co)
{
    int idx = blockIdx.x * 256 + threadIdx.x;
    int total = BATCH * co * HW;
    if (idx >= total) return;
    int b = idx / (co << 10);
    int r = idx - b * (co << 10);
    int c = r >> 10, i = r & 1023;
    float v;
    if (c < co_conv) {
        v = g_conv[((b * co_conv + c) << 10) + i];
    } else {
        int cc = c - co_conv;
        float a0 = g_attn[((b * 4 + 0) << 10) + i];
        float a1 = g_attn[((b * 4 + 1) << 10) + i];
        float a2 = g_attn[((b * 4 + 2) << 10) + i];
        float a3 = g_attn[((b * 4 + 3) << 10) + i];
        v = attn_b[cc] + attn_w[cc * 4] * a0 + attn_w[cc * 4 + 1] * a1
          + attn_w[cc * 4 + 2] * a2 + attn_w[cc * 4 + 3] * a3;
    }
    g_x[idx] = fmaxf(v, 0.f);
}

// ---------------------------------------------------------------------------
// Final: layer2 concat (co_conv=2) + 1x1 attn conv + FC(6->1), no ReLU.
// ---------------------------------------------------------------------------
__global__ __launch_bounds__(256) void final_kernel(
    const float* __restrict__ attn_w, const float* __restrict__ attn_b,
    const float* __restrict__ fc_w, const float* __restrict__ fc_b,
    float* __restrict__ out)
{
    int idx = blockIdx.x * 256 + threadIdx.x;
    if (idx >= BATCH * HW) return;
    int b = idx >> 10, i = idx & 1023;
    float r = fc_b[0];
    r = fmaf(fc_w[0], g_conv[((b * 2 + 0) << 10) + i], r);
    r = fmaf(fc_w[1], g_conv[((b * 2 + 1) << 10) + i], r);
    float a0 = g_attn[((b * 4 + 0) << 10) + i];
    float a1 = g_attn[((b * 4 + 1) << 10) + i];
    float a2 = g_attn[((b * 4 + 2) << 10) + i];
    float a3 = g_attn[((b * 4 + 3) << 10) + i];
#pragma unroll
    for (int c = 0; c < 4; c++) {
        float v = attn_b[c] + attn_w[c * 4] * a0 + attn_w[c * 4 + 1] * a1
                + attn_w[c * 4 + 2] * a2 + attn_w[c * 4 + 3] * a3;
        r = fmaf(fc_w[2 + c], v, r);
    }
    out[idx] = r;
}

// ---------------------------------------------------------------------------
// Launch: inputs in metadata order:
// 0:x, per layer l: [1+8l..8+8l] = conv_w, conv_b, qkv_w, qkv_b,
//                                  attn_w, attn_b, relw, relh; 25:fc_w, 26:fc_b
// ---------------------------------------------------------------------------
extern "C" void kernel_launch(void* const* d_in, const int* in_sizes, int n_in,
                              void* d_out, int out_size)
{
    (void)in_sizes; (void)n_in; (void)out_size;
    const float* x = (const float*)d_in[0];
    auto L = [&](int l, int k) { return (const float*)d_in[1 + l * 8 + k]; };
    float* out = (float*)d_out;

    // ---- layer 0: ci=8, co=32 (conv_oc=28) ----
    conv_fused<<<dim3(16, 8), 256>>>(x, 0, 8, L(0, 0), L(0, 1), 28, L(0, 2), L(0, 3));
    attn_kernel<<<dim3(4, 4, 16), 256>>>(L(0, 6), L(0, 7));
    combine_mid<<<(BATCH * 32 * HW + 255) / 256, 256>>>(28, L(0, 4), L(0, 5), 32);

    // ---- layer 1: ci=32, co=32 (conv_oc=28) ----
    conv_fused<<<dim3(16, 8), 256>>>(nullptr, 1, 32, L(1, 0), L(1, 1), 28, L(1, 2), L(1, 3));
    attn_kernel<<<dim3(4, 4, 16), 256>>>(L(1, 6), L(1, 7));
    combine_mid<<<(BATCH * 32 * HW + 255) / 256, 256>>>(28, L(1, 4), L(1, 5), 32);

    // ---- layer 2: ci=32, co=6 (conv_oc=2), fused with FC ----
    conv_fused<<<dim3(16, 5), 256>>>(nullptr, 1, 32, L(2, 0), L(2, 1), 2, L(2, 2), L(2, 3));
    attn_kernel<<<dim3(4, 4, 16), 256>>>(L(2, 6), L(2, 7));
    final_kernel<<<(BATCH * HW + 255) / 256, 256>>>(
        L(2, 4), L(2, 5), (const float*)d_in[25], (const float*)d_in[26], out);
}

// round 4
// speedup vs baseline: 1.3645x; 1.3645x over previous
#include <cuda_runtime.h>
#include <cuda_bf16.h>

// ---------------------------------------------------------------------------
// AAconv: 3x (AugmentedConv + ReLU[first two]) + FC head.
// Shapes fixed: B=16, S=32 (HW=1024), DK=16, DV=4, NH=4 => dkh=4, dvh=1.
// Layers: (ci, co) = (8,32), (32,32), (32,6); conv_oc = co-4; qkv_oc = 36.
// ---------------------------------------------------------------------------

#define BATCH 16
#define HW 1024

// Scratch (device globals; allocation-free per harness rules)
__device__ float g_x[BATCH * 32 * HW];      // layer intermediate (max co=32)
__device__ float g_conv[BATCH * 28 * HW];   // conv branch (max co_conv=28)
__device__ float g_qkv[BATCH * 36 * HW];    // qkv buffer
__device__ float g_attn[BATCH * 4 * HW];    // per-head attention output (dvh=1)

// ---------------------------------------------------------------------------
// Fused 3x3 conv: conv_out (CO_CONV ch) + qkv (36 ch).
// Grid: (batch, oc-group-of-4, row-half). Block: 128 thr = 16 rows x 8 xq.
// Each thread: 4 oc x 4 px register accumulators. ci chunks of 8.
// ---------------------------------------------------------------------------
__global__ __launch_bounds__(128) void conv_fused(
    const float* __restrict__ in_ext, int use_internal, int CI,
    const float* __restrict__ wc, const float* __restrict__ bc, int CO_CONV,
    const float* __restrict__ wq, const float* __restrict__ bq)
{
    const float* __restrict__ in = use_internal ? g_x : in_ext;
    const int b    = blockIdx.x;
    const int oc0  = blockIdx.y * 4;
    const int half = blockIdx.z;           // 0/1 -> rows [0,16) / [16,32)
    const int OC_TOT = CO_CONV + 36;

    __shared__ float tile[8][18][35];      // 16 rows + halo, +1 pad col
    __shared__ float ws[4][8][9];
    __shared__ float wb[4];

    const int tid = threadIdx.x;
    if (tid < 4) {
        int oc = oc0 + tid;
        float bv = 0.f;
        if (oc < OC_TOT) bv = (oc < CO_CONV) ? bc[oc] : bq[oc - CO_CONV];
        wb[tid] = bv;
    }

    float acc[4][4];
#pragma unroll
    for (int o = 0; o < 4; o++)
#pragma unroll
        for (int p = 0; p < 4; p++) acc[o][p] = 0.f;

    const int yl = tid >> 3;               // 0..15 local row
    const int xq = (tid & 7) * 4;          // 0,4,...,28
    const int y  = half * 16 + yl;         // global output row

    for (int ci0 = 0; ci0 < CI; ci0 += 8) {
        // weights for this (oc-group, ci-chunk): 4*8*9 = 288 values
        for (int w = tid; w < 4 * 8 * 9; w += 128) {
            int o = w / 72;
            int r = w - o * 72;
            int c = r / 9, tap = r - c * 9;
            int oc = oc0 + o;
            float val = 0.f;
            if (oc < OC_TOT) {
                if (oc < CO_CONV) val = wc[(oc * CI + ci0 + c) * 9 + tap];
                else              val = wq[((oc - CO_CONV) * CI + ci0 + c) * 9 + tap];
            }
            ws[o][c][tap] = val;
        }
        // input strip: rows [half*16-1, half*16+17), 18 rows x 34 cols, 8 ch
        for (int e = tid; e < 8 * 18 * 34; e += 128) {
            int c = e / 612;
            int r = e - c * 612;
            int yy = r / 34, xx = r - yy * 34;
            int gy = half * 16 - 1 + yy, gx = xx - 1;
            float v = 0.f;
            if ((unsigned)gy < 32u && (unsigned)gx < 32u)
                v = in[((b * CI + ci0 + c) << 10) + gy * 32 + gx];
            tile[c][yy][xx] = v;
        }
        __syncthreads();

#pragma unroll
        for (int c = 0; c < 8; c++) {
            float p[3][6];
#pragma unroll
            for (int dy = 0; dy < 3; dy++)
#pragma unroll
                for (int dx = 0; dx < 6; dx++)
                    p[dy][dx] = tile[c][yl + dy][xq + dx];
#pragma unroll
            for (int o = 0; o < 4; o++) {
                float w0 = ws[o][c][0], w1 = ws[o][c][1], w2 = ws[o][c][2];
                float w3 = ws[o][c][3], w4 = ws[o][c][4], w5 = ws[o][c][5];
                float w6 = ws[o][c][6], w7 = ws[o][c][7], w8 = ws[o][c][8];
#pragma unroll
                for (int px = 0; px < 4; px++) {
                    float a = acc[o][px];
                    a = fmaf(w0, p[0][px], a);
                    a = fmaf(w1, p[0][px + 1], a);
                    a = fmaf(w2, p[0][px + 2], a);
                    a = fmaf(w3, p[1][px], a);
                    a = fmaf(w4, p[1][px + 1], a);
                    a = fmaf(w5, p[1][px + 2], a);
                    a = fmaf(w6, p[2][px], a);
                    a = fmaf(w7, p[2][px + 1], a);
                    a = fmaf(w8, p[2][px + 2], a);
                    acc[o][px] = a;
                }
            }
        }
        __syncthreads();
    }

#pragma unroll
    for (int o = 0; o < 4; o++) {
        int oc = oc0 + o;
        if (oc >= OC_TOT) continue;
        float bv = wb[o];
        float4 v4 = make_float4(acc[o][0] + bv, acc[o][1] + bv,
                                acc[o][2] + bv, acc[o][3] + bv);
        float* dst = (oc < CO_CONV)
            ? (g_conv + ((b * CO_CONV + oc) << 10))
            : (g_qkv  + ((b * 36 + (oc - CO_CONV)) << 10));
        *reinterpret_cast<float4*>(dst + y * 32 + xq) = v4;
    }
}

// ---------------------------------------------------------------------------
// Attention, queries-in-lanes layout.
// Warp handles 32 consecutive queries: i = qbase + lane -> x = qbase>>5
// (warp-uniform), y = lane. All K/V/rel_h smem reads are broadcasts.
// logit(i,j=(xk,yk)) = q.k_j + RW[yk] + RH(xk), RW statically indexed in regs.
// q pre-scaled by 0.5*log2(e); softmax via exp2f (chunked two-pass, online
// merge across 32-key chunks).
// ---------------------------------------------------------------------------
__global__ __launch_bounds__(128) void attn_kernel(
    const float* __restrict__ relw, const float* __restrict__ relh)
{
    const int chunk = blockIdx.x;  // 0..7 (128 queries each)
    const int n = blockIdx.y;      // head
    const int b = blockIdx.z;

    __shared__ float4 ks4[1024];
    __shared__ float  vs[1024];
    __shared__ float4 rws4[63];
    __shared__ float4 rhs4[63];

    const int tid = threadIdx.x;
    const float* kbase = g_qkv + ((size_t)(b * 36 + 16 + n * 4) << 10);
    const float* vbase = g_qkv + ((size_t)(b * 36 + 32 + n) << 10);
    for (int j = tid; j < 1024; j += 128) {
        ks4[j] = make_float4(kbase[j], kbase[j + 1024], kbase[j + 2048], kbase[j + 3072]);
        vs[j] = vbase[j];
    }
    if (tid < 63) {
        rws4[tid] = reinterpret_cast<const float4*>(relw)[tid];
        rhs4[tid] = reinterpret_cast<const float4*>(relh)[tid];
    }
    __syncthreads();

    const int warp = tid >> 5, lane = tid & 31;
    const int qbase0 = chunk * 128 + warp * 32;   // multiple of 32
    const int i = qbase0 + lane;
    const int x = qbase0 >> 5;                    // warp-uniform
    // y = lane

    const float* qptr = g_qkv + ((size_t)(b * 36 + n * 4) << 10);
    const float C = 0.7213475204444817f;          // 0.5 * log2(e)
    const float q0 = qptr[i]        * C;
    const float q1 = qptr[i + 1024] * C;
    const float q2 = qptr[i + 2048] * C;
    const float q3 = qptr[i + 3072] * C;

    // RW[yk] = q . rel_w[yk - y + 31], y = lane. Statically indexed registers.
    float RW[32];
#pragma unroll
    for (int yk = 0; yk < 32; yk++) {
        float4 r = rws4[yk - lane + 31];
        RW[yk] = fmaf(q0, r.x, fmaf(q1, r.y, fmaf(q2, r.z, q3 * r.w)));
    }

    float m = -1e30f, l = 0.f, a = 0.f;
    for (int xk = 0; xk < 32; xk++) {
        float4 rh = rhs4[xk - x + 31];            // broadcast
        float RH = fmaf(q0, rh.x, fmaf(q1, rh.y, fmaf(q2, rh.z, q3 * rh.w)));
        float s[32];
        float cmax = -1e30f;
#pragma unroll
        for (int yk = 0; yk < 32; yk++) {
            float4 kk = ks4[xk * 32 + yk];        // broadcast
            float t = RH + RW[yk];
            t = fmaf(q0, kk.x, fmaf(q1, kk.y, fmaf(q2, kk.z, fmaf(q3, kk.w, t))));
            s[yk] = t;
            cmax = fmaxf(cmax, t);
        }
        float mnew = fmaxf(m, cmax);
        float scale = exp2f(m - mnew);
        l *= scale; a *= scale; m = mnew;
#pragma unroll
        for (int yk = 0; yk < 32; yk++) {
            float p = exp2f(s[yk] - m);
            l += p;
            a = fmaf(p, vs[xk * 32 + yk], a);     // broadcast
        }
    }
    g_attn[((b * 4 + n) << 10) + i] = a / l;
}

// ---------------------------------------------------------------------------
// Mid-layer combine: concat(conv_out, 1x1conv(attn)) + ReLU -> g_x
// ---------------------------------------------------------------------------
__global__ __launch_bounds__(256) void combine_mid(
    int co_conv, const float* __restrict__ attn_w,
    const float* __restrict__ attn_b, int co)
{
    int idx = blockIdx.x * 256 + threadIdx.x;
    int total = BATCH * co * HW;
    if (idx >= total) return;
    int b = idx / (co << 10);
    int r = idx - b * (co << 10);
    int c = r >> 10, i = r & 1023;
    float v;
    if (c < co_conv) {
        v = g_conv[((b * co_conv + c) << 10) + i];
    } else {
        int cc = c - co_conv;
        float a0 = g_attn[((b * 4 + 0) << 10) + i];
        float a1 = g_attn[((b * 4 + 1) << 10) + i];
        float a2 = g_attn[((b * 4 + 2) << 10) + i];
        float a3 = g_attn[((b * 4 + 3) << 10) + i];
        v = attn_b[cc] + attn_w[cc * 4] * a0 + attn_w[cc * 4 + 1] * a1
          + attn_w[cc * 4 + 2] * a2 + attn_w[cc * 4 + 3] * a3;
    }
    g_x[idx] = fmaxf(v, 0.f);
}

// ---------------------------------------------------------------------------
// Final: layer2 concat (co_conv=2) + 1x1 attn conv + FC(6->1), no ReLU.
// ---------------------------------------------------------------------------
__global__ __launch_bounds__(256) void final_kernel(
    const float* __restrict__ attn_w, const float* __restrict__ attn_b,
    const float* __restrict__ fc_w, const float* __restrict__ fc_b,
    float* __restrict__ out)
{
    int idx = blockIdx.x * 256 + threadIdx.x;
    if (idx >= BATCH * HW) return;
    int b = idx >> 10, i = idx & 1023;
    float r = fc_b[0];
    r = fmaf(fc_w[0], g_conv[((b * 2 + 0) << 10) + i], r);
    r = fmaf(fc_w[1], g_conv[((b * 2 + 1) << 10) + i], r);
    float a0 = g_attn[((b * 4 + 0) << 10) + i];
    float a1 = g_attn[((b * 4 + 1) << 10) + i];
    float a2 = g_attn[((b * 4 + 2) << 10) + i];
    float a3 = g_attn[((b * 4 + 3) << 10) + i];
#pragma unroll
    for (int c = 0; c < 4; c++) {
        float v = attn_b[c] + attn_w[c * 4] * a0 + attn_w[c * 4 + 1] * a1
                + attn_w[c * 4 + 2] * a2 + attn_w[c * 4 + 3] * a3;
        r = fmaf(fc_w[2 + c], v, r);
    }
    out[idx] = r;
}

// ---------------------------------------------------------------------------
// Launch: inputs in metadata order:
// 0:x, per layer l: [1+8l..8+8l] = conv_w, conv_b, qkv_w, qkv_b,
//                                  attn_w, attn_b, relw, relh; 25:fc_w, 26:fc_b
// ---------------------------------------------------------------------------
extern "C" void kernel_launch(void* const* d_in, const int* in_sizes, int n_in,
                              void* d_out, int out_size)
{
    (void)in_sizes; (void)n_in; (void)out_size;
    const float* x = (const float*)d_in[0];
    auto L = [&](int l, int k) { return (const float*)d_in[1 + l * 8 + k]; };
    float* out = (float*)d_out;

    // ---- layer 0: ci=8, co=32 (conv_oc=28); oc_tot=64 -> 16 groups of 4 ----
    conv_fused<<<dim3(16, 16, 2), 128>>>(x, 0, 8, L(0, 0), L(0, 1), 28, L(0, 2), L(0, 3));
    attn_kernel<<<dim3(8, 4, 16), 128>>>(L(0, 6), L(0, 7));
    combine_mid<<<(BATCH * 32 * HW + 255) / 256, 256>>>(28, L(0, 4), L(0, 5), 32);

    // ---- layer 1: ci=32, co=32 (conv_oc=28) ----
    conv_fused<<<dim3(16, 16, 2), 128>>>(nullptr, 1, 32, L(1, 0), L(1, 1), 28, L(1, 2), L(1, 3));
    attn_kernel<<<dim3(8, 4, 16), 128>>>(L(1, 6), L(1, 7));
    combine_mid<<<(BATCH * 32 * HW + 255) / 256, 256>>>(28, L(1, 4), L(1, 5), 32);

    // ---- layer 2: ci=32, co=6 (conv_oc=2); oc_tot=38 -> 10 groups of 4 ----
    conv_fused<<<dim3(16, 10, 2), 128>>>(nullptr, 1, 32, L(2, 0), L(2, 1), 2, L(2, 2), L(2, 3));
    attn_kernel<<<dim3(8, 4, 16), 128>>>(L(2, 6), L(2, 7));
    final_kernel<<<(BATCH * HW + 255) / 256, 256>>>(
        L(2, 4), L(2, 5), (const float*)d_in[25], (const float*)d_in[26], out);
}

// round 5
// speedup vs baseline: 1.6342x; 1.1976x over previous
#include <cuda_runtime.h>
#include <cuda_bf16.h>

// ---------------------------------------------------------------------------
// AAconv: 3x (AugmentedConv + ReLU[first two]) + FC head.
// Shapes fixed: B=16, S=32 (HW=1024), DK=16, DV=4, NH=4 => dkh=4, dvh=1.
// Layers: (ci, co) = (8,32), (32,32), (32,6); conv_oc = co-4; qkv_oc = 36.
// ---------------------------------------------------------------------------

#define BATCH 16
#define HW 1024

// Scratch (device globals; allocation-free per harness rules)
__device__ __align__(16) float g_x[BATCH * 32 * HW];    // layer intermediate
__device__ __align__(16) float g_conv[BATCH * 28 * HW]; // conv branch
__device__ __align__(16) float g_qkv[BATCH * 36 * HW];  // qkv buffer
__device__ __align__(16) float g_attn[BATCH * 4 * HW];  // per-head attn out

// ---------------------------------------------------------------------------
// Fused 3x3 conv: conv_out (CO_CONV ch) + qkv (36 ch).
// Grid: (batch, oc-group-of-4, row-half). Block: 128 thr = 16 rows x 8 xq.
// Tile has NO column halo (block spans full width; borders are zero-pad,
// handled by predicated selects in the compute loop). Loader is float4
// vectorized: 1 LDG.128 + 4 STS.32 per 4 elems, cheap index math.
// ---------------------------------------------------------------------------
__global__ __launch_bounds__(128) void conv_fused(
    const float* __restrict__ in_ext, int use_internal, int CI,
    const float* __restrict__ wc, const float* __restrict__ bc, int CO_CONV,
    const float* __restrict__ wq, const float* __restrict__ bq)
{
    const float* __restrict__ in = use_internal ? g_x : in_ext;
    const int b    = blockIdx.x;
    const int oc0  = blockIdx.y * 4;
    const int half = blockIdx.z;           // 0/1 -> rows [0,16) / [16,32)
    const int OC_TOT = CO_CONV + 36;

    __shared__ float tile[8][18][33];      // stride 33 (33 mod 32 = 1): conflict-free
    __shared__ float ws[4][8][9];
    __shared__ float wb[4];

    const int tid = threadIdx.x;
    if (tid < 4) {
        int oc = oc0 + tid;
        float bv = 0.f;
        if (oc < OC_TOT) bv = (oc < CO_CONV) ? bc[oc] : bq[oc - CO_CONV];
        wb[tid] = bv;
    }

    float acc[4][4];
#pragma unroll
    for (int o = 0; o < 4; o++)
#pragma unroll
        for (int p = 0; p < 4; p++) acc[o][p] = 0.f;

    const int yl = tid >> 3;               // 0..15 local row
    const int xq = (tid & 7) * 4;          // 0,4,...,28
    const int y  = half * 16 + yl;         // global output row
    const int row0 = half * 16 - 1;        // first tile row (global)

    for (int ci0 = 0; ci0 < CI; ci0 += 8) {
        // weights: 72 threads, each loads 4 oc values for its (c, tap)
        if (tid < 72) {
            int c = tid / 9, tap = tid - c * 9;
#pragma unroll
            for (int o = 0; o < 4; o++) {
                int oc = oc0 + o;
                float val = 0.f;
                if (oc < OC_TOT) {
                    if (oc < CO_CONV) val = __ldg(wc + (oc * CI + ci0 + c) * 9 + tap);
                    else              val = __ldg(wq + ((oc - CO_CONV) * CI + ci0 + c) * 9 + tap);
                }
                ws[o][c][tap] = val;
            }
        }
        // input strip: 8 ch x 18 rows x 32 cols, float4 vectorized.
        // 8*18*8 = 1152 vec slots, 9 iterations per thread.
#pragma unroll
        for (int e = tid; e < 1152; e += 128) {
            int c  = e / 144;
            int r  = e - c * 144;
            int yy = r >> 3;
            int vx = (r & 7) << 2;
            int gy = row0 + yy;
            float4 v = make_float4(0.f, 0.f, 0.f, 0.f);
            if ((unsigned)gy < 32u)
                v = *reinterpret_cast<const float4*>(
                        in + ((b * CI + ci0 + c) << 10) + (gy << 5) + vx);
            float* t = &tile[c][yy][vx];
            t[0] = v.x; t[1] = v.y; t[2] = v.z; t[3] = v.w;
        }
        __syncthreads();

#pragma unroll
        for (int c = 0; c < 8; c++) {
            // inputs for output cols xq..xq+3: input cols xq-1 .. xq+4
            float p[3][6];
#pragma unroll
            for (int dy = 0; dy < 3; dy++) {
                const float* trow = tile[c][yl + dy];
                p[dy][0] = (xq > 0)  ? trow[xq - 1] : 0.f;   // left zero-pad
#pragma unroll
                for (int dx = 1; dx < 5; dx++)
                    p[dy][dx] = trow[xq - 1 + dx];
                p[dy][5] = (xq < 28) ? trow[xq + 4] : 0.f;   // right zero-pad
            }
#pragma unroll
            for (int o = 0; o < 4; o++) {
                float w0 = ws[o][c][0], w1 = ws[o][c][1], w2 = ws[o][c][2];
                float w3 = ws[o][c][3], w4 = ws[o][c][4], w5 = ws[o][c][5];
                float w6 = ws[o][c][6], w7 = ws[o][c][7], w8 = ws[o][c][8];
#pragma unroll
                for (int px = 0; px < 4; px++) {
                    float a = acc[o][px];
                    a = fmaf(w0, p[0][px], a);
                    a = fmaf(w1, p[0][px + 1], a);
                    a = fmaf(w2, p[0][px + 2], a);
                    a = fmaf(w3, p[1][px], a);
                    a = fmaf(w4, p[1][px + 1], a);
                    a = fmaf(w5, p[1][px + 2], a);
                    a = fmaf(w6, p[2][px], a);
                    a = fmaf(w7, p[2][px + 1], a);
                    a = fmaf(w8, p[2][px + 2], a);
                    acc[o][px] = a;
                }
            }
        }
        __syncthreads();
    }

#pragma unroll
    for (int o = 0; o < 4; o++) {
        int oc = oc0 + o;
        if (oc >= OC_TOT) continue;
        float bv = wb[o];
        float4 v4 = make_float4(acc[o][0] + bv, acc[o][1] + bv,
                                acc[o][2] + bv, acc[o][3] + bv);
        float* dst = (oc < CO_CONV)
            ? (g_conv + ((b * CO_CONV + oc) << 10))
            : (g_qkv  + ((b * 36 + (oc - CO_CONV)) << 10));
        *reinterpret_cast<float4*>(dst + y * 32 + xq) = v4;
    }
}

// ---------------------------------------------------------------------------
// Attention, queries-in-lanes layout (unchanged from round 4 — it delivered
// the 304->223 win; MUFU exp floor ~15us/layer bounds further gains).
// Warp handles 32 consecutive queries: i = qbase + lane -> x warp-uniform,
// y = lane. All K/V/rel_h smem reads are broadcasts. q pre-scaled by
// 0.5*log2(e); exp2f online-merge softmax per 32-key chunk.
// ---------------------------------------------------------------------------
__global__ __launch_bounds__(128) void attn_kernel(
    const float* __restrict__ relw, const float* __restrict__ relh)
{
    const int chunk = blockIdx.x;  // 0..7 (128 queries each)
    const int n = blockIdx.y;      // head
    const int b = blockIdx.z;

    __shared__ float4 ks4[1024];
    __shared__ float  vs[1024];
    __shared__ float4 rws4[63];
    __shared__ float4 rhs4[63];

    const int tid = threadIdx.x;
    const float* kbase = g_qkv + ((size_t)(b * 36 + 16 + n * 4) << 10);
    const float* vbase = g_qkv + ((size_t)(b * 36 + 32 + n) << 10);
    for (int j = tid; j < 1024; j += 128) {
        ks4[j] = make_float4(kbase[j], kbase[j + 1024], kbase[j + 2048], kbase[j + 3072]);
        vs[j] = vbase[j];
    }
    if (tid < 63) {
        rws4[tid] = reinterpret_cast<const float4*>(relw)[tid];
        rhs4[tid] = reinterpret_cast<const float4*>(relh)[tid];
    }
    __syncthreads();

    const int warp = tid >> 5, lane = tid & 31;
    const int qbase0 = chunk * 128 + warp * 32;   // multiple of 32
    const int i = qbase0 + lane;
    const int x = qbase0 >> 5;                    // warp-uniform
    // y = lane

    const float* qptr = g_qkv + ((size_t)(b * 36 + n * 4) << 10);
    const float C = 0.7213475204444817f;          // 0.5 * log2(e)
    const float q0 = qptr[i]        * C;
    const float q1 = qptr[i + 1024] * C;
    const float q2 = qptr[i + 2048] * C;
    const float q3 = qptr[i + 3072] * C;

    // RW[yk] = q . rel_w[yk - y + 31], y = lane. Statically indexed registers.
    float RW[32];
#pragma unroll
    for (int yk = 0; yk < 32; yk++) {
        float4 r = rws4[yk - lane + 31];
        RW[yk] = fmaf(q0, r.x, fmaf(q1, r.y, fmaf(q2, r.z, q3 * r.w)));
    }

    float m = -1e30f, l = 0.f, a = 0.f;
    for (int xk = 0; xk < 32; xk++) {
        float4 rh = rhs4[xk - x + 31];            // broadcast
        float RH = fmaf(q0, rh.x, fmaf(q1, rh.y, fmaf(q2, rh.z, q3 * rh.w)));
        float s[32];
        float cmax = -1e30f;
#pragma unroll
        for (int yk = 0; yk < 32; yk++) {
            float4 kk = ks4[xk * 32 + yk];        // broadcast
            float t = RH + RW[yk];
            t = fmaf(q0, kk.x, fmaf(q1, kk.y, fmaf(q2, kk.z, fmaf(q3, kk.w, t))));
            s[yk] = t;
            cmax = fmaxf(cmax, t);
        }
        float mnew = fmaxf(m, cmax);
        float scale = exp2f(m - mnew);
        l *= scale; a *= scale; m = mnew;
#pragma unroll
        for (int yk = 0; yk < 32; yk++) {
            float p = exp2f(s[yk] - m);
            l += p;
            a = fmaf(p, vs[xk * 32 + yk], a);     // broadcast
        }
    }
    g_attn[((b * 4 + n) << 10) + i] = a / l;
}

// ---------------------------------------------------------------------------
// Mid-layer combine: concat(conv_out, 1x1conv(attn)) + ReLU -> g_x
// ---------------------------------------------------------------------------
__global__ __launch_bounds__(256) void combine_mid(
    int co_conv, const float* __restrict__ attn_w,
    const float* __restrict__ attn_b, int co)
{
    int idx = blockIdx.x * 256 + threadIdx.x;
    int total = BATCH * co * HW;
    if (idx >= total) return;
    int b = idx / (co << 10);
    int r = idx - b * (co << 10);
    int c = r >> 10, i = r & 1023;
    float v;
    if (c < co_conv) {
        v = g_conv[((b * co_conv + c) << 10) + i];
    } else {
        int cc = c - co_conv;
        float a0 = g_attn[((b * 4 + 0) << 10) + i];
        float a1 = g_attn[((b * 4 + 1) << 10) + i];
        float a2 = g_attn[((b * 4 + 2) << 10) + i];
        float a3 = g_attn[((b * 4 + 3) << 10) + i];
        v = attn_b[cc] + attn_w[cc * 4] * a0 + attn_w[cc * 4 + 1] * a1
          + attn_w[cc * 4 + 2] * a2 + attn_w[cc * 4 + 3] * a3;
    }
    g_x[idx] = fmaxf(v, 0.f);
}

// ---------------------------------------------------------------------------
// Final: layer2 concat (co_conv=2) + 1x1 attn conv + FC(6->1), no ReLU.
// ---------------------------------------------------------------------------
__global__ __launch_bounds__(256) void final_kernel(
    const float* __restrict__ attn_w, const float* __restrict__ attn_b,
    const float* __restrict__ fc_w, const float* __restrict__ fc_b,
    float* __restrict__ out)
{
    int idx = blockIdx.x * 256 + threadIdx.x;
    if (idx >= BATCH * HW) return;
    int b = idx >> 10, i = idx & 1023;
    float r = fc_b[0];
    r = fmaf(fc_w[0], g_conv[((b * 2 + 0) << 10) + i], r);
    r = fmaf(fc_w[1], g_conv[((b * 2 + 1) << 10) + i], r);
    float a0 = g_attn[((b * 4 + 0) << 10) + i];
    float a1 = g_attn[((b * 4 + 1) << 10) + i];
    float a2 = g_attn[((b * 4 + 2) << 10) + i];
    float a3 = g_attn[((b * 4 + 3) << 10) + i];
#pragma unroll
    for (int c = 0; c < 4; c++) {
        float v = attn_b[c] + attn_w[c * 4] * a0 + attn_w[c * 4 + 1] * a1
                + attn_w[c * 4 + 2] * a2 + attn_w[c * 4 + 3] * a3;
        r = fmaf(fc_w[2 + c], v, r);
    }
    out[idx] = r;
}

// ---------------------------------------------------------------------------
// Launch: inputs in metadata order:
// 0:x, per layer l: [1+8l..8+8l] = conv_w, conv_b, qkv_w, qkv_b,
//                                  attn_w, attn_b, relw, relh; 25:fc_w, 26:fc_b
// ---------------------------------------------------------------------------
extern "C" void kernel_launch(void* const* d_in, const int* in_sizes, int n_in,
                              void* d_out, int out_size)
{
    (void)in_sizes; (void)n_in; (void)out_size;
    const float* x = (const float*)d_in[0];
    auto L = [&](int l, int k) { return (const float*)d_in[1 + l * 8 + k]; };
    float* out = (float*)d_out;

    // ---- layer 0: ci=8, co=32 (conv_oc=28); oc_tot=64 -> 16 groups of 4 ----
    conv_fused<<<dim3(16, 16, 2), 128>>>(x, 0, 8, L(0, 0), L(0, 1), 28, L(0, 2), L(0, 3));
    attn_kernel<<<dim3(8, 4, 16), 128>>>(L(0, 6), L(0, 7));
    combine_mid<<<(BATCH * 32 * HW + 255) / 256, 256>>>(28, L(0, 4), L(0, 5), 32);

    // ---- layer 1: ci=32, co=32 (conv_oc=28) ----
    conv_fused<<<dim3(16, 16, 2), 128>>>(nullptr, 1, 32, L(1, 0), L(1, 1), 28, L(1, 2), L(1, 3));
    attn_kernel<<<dim3(8, 4, 16), 128>>>(L(1, 6), L(1, 7));
    combine_mid<<<(BATCH * 32 * HW + 255) / 256, 256>>>(28, L(1, 4), L(1, 5), 32);

    // ---- layer 2: ci=32, co=6 (conv_oc=2); oc_tot=38 -> 10 groups of 4 ----
    conv_fused<<<dim3(16, 10, 2), 128>>>(nullptr, 1, 32, L(2, 0), L(2, 1), 2, L(2, 2), L(2, 3));
    attn_kernel<<<dim3(8, 4, 16), 128>>>(L(2, 6), L(2, 7));
    final_kernel<<<(BATCH * HW + 255) / 256, 256>>>(
        L(2, 4), L(2, 5), (const float*)d_in[25], (const float*)d_in[26], out);
}